// round 9
// baseline (speedup 1.0000x reference)
#include <cuda_runtime.h>
#include <cuda_bf16.h>
#include <math.h>

#define NN      100000
#define F_IN    256
#define HID     64
#define H1      8
#define C1      8
#define NC      40
#define E_MAX   1700000
#define NEG_SLOPE 0.2f
#define AST2    258     // transposed-A row stride (floats): even (8B pairs), mod 32 = 2

// ---------------- packed f32x2 helpers ----------------------------------------
__device__ __forceinline__ unsigned long long ffma2(
    unsigned long long a, unsigned long long b, unsigned long long c) {
    unsigned long long d;
    asm("fma.rn.f32x2 %0, %1, %2, %3;" : "=l"(d) : "l"(a), "l"(b), "l"(c));
    return d;
}
__device__ __forceinline__ unsigned long long pack2(float lo, float hi) {
    unsigned long long d;
    asm("mov.b64 %0, {%1, %2};" : "=l"(d) : "f"(lo), "f"(hi));
    return d;
}
__device__ __forceinline__ void unpack2(unsigned long long v, float& lo, float& hi) {
    asm("mov.b64 {%0, %1}, %2;" : "=f"(lo), "=f"(hi) : "l"(v));
}

// ---------------- scratch -----------------------------------------------------
__device__ int   g_is64;
__device__ int   g_deg[NN];
__device__ int   g_rowptr[NN + 1];
__device__ int   g_fill[NN];
__device__ int   g_col[E_MAX];
__device__ int   g_bsum[256];
__device__ float g_h1[(long)NN * HID];
__device__ float g_as1[NN * H1];
__device__ float g_ad1[NN * H1];
__device__ float g_h1o[(long)NN * HID];
__device__ float g_h2[(long)NN * NC];
__device__ float g_as2[NN];
__device__ float g_ad2[NN];

// -------- init: zero degrees + edge dtype detection (block 0) -----------------
__global__ void k_init(const void* ei, int EC) {
    int i = blockIdx.x * blockDim.x + threadIdx.x;
    if (i < NN) g_deg[i] = 0;
    if (blockIdx.x == 0) {
        __shared__ int bad;
        if (threadIdx.x == 0) bad = 0;
        __syncthreads();
        const long long* p = (const long long*)ei;
        int n = EC < 256 ? EC : 256;
        if ((int)threadIdx.x < n) {
            long long v = p[threadIdx.x];
            if (v < 0 || v >= NN) atomicExch(&bad, 1);
        }
        __syncthreads();
        if (threadIdx.x == 0) g_is64 = bad ? 0 : 1;
    }
}

__device__ __forceinline__ int edge_at(const void* ei, int idx) {
    return g_is64 ? (int)((const long long*)ei)[idx] : ((const int*)ei)[idx];
}

// ---------------- CSR build ---------------------------------------------------
__global__ void k_hist(const void* ei, int EC) {
    int i = blockIdx.x * blockDim.x + threadIdx.x;
    if (i < EC) {
        int d = edge_at(ei, EC + i);
        if (d >= 0 && d < NN) atomicAdd(&g_deg[d], 1);
    }
}

__global__ void k_scan_block() {
    __shared__ int ws[32];
    int tid = threadIdx.x;
    int gid = blockIdx.x * 1024 + tid;
    int v = (gid < NN) ? g_deg[gid] : 0;
    int x = v;
    #pragma unroll
    for (int o = 1; o < 32; o <<= 1) {
        int t = __shfl_up_sync(0xffffffffu, x, o);
        if ((tid & 31) >= o) x += t;
    }
    if ((tid & 31) == 31) ws[tid >> 5] = x;
    __syncthreads();
    if (tid < 32) {
        int w = ws[tid];
        int y = w;
        #pragma unroll
        for (int o = 1; o < 32; o <<= 1) {
            int t = __shfl_up_sync(0xffffffffu, y, o);
            if (tid >= o) y += t;
        }
        ws[tid] = y - w;
    }
    __syncthreads();
    int incl = x + ws[tid >> 5];
    if (gid < NN) g_rowptr[gid] = incl - v;
    if (tid == 1023) g_bsum[blockIdx.x] = incl;
}

__global__ void k_scan_tops(int nblocks) {
    int lane = threadIdx.x;
    int run = 0;
    for (int base = 0; base < nblocks; base += 32) {
        int idx = base + lane;
        int v = (idx < nblocks) ? g_bsum[idx] : 0;
        int x = v;
        #pragma unroll
        for (int o = 1; o < 32; o <<= 1) {
            int t = __shfl_up_sync(0xffffffffu, x, o);
            if (lane >= o) x += t;
        }
        if (idx < nblocks) g_bsum[idx] = run + x - v;
        run += __shfl_sync(0xffffffffu, x, 31);
    }
}

__global__ void k_scan_fix(int EC) {
    int gid = blockIdx.x * 1024 + threadIdx.x;
    if (gid < NN) {
        int v = g_rowptr[gid] + g_bsum[gid >> 10];
        g_rowptr[gid] = v;
        g_fill[gid] = v;
    }
    if (gid == 0) g_rowptr[NN] = EC;
}

__global__ void k_scatter(const void* ei, int EC) {
    int i = blockIdx.x * blockDim.x + threadIdx.x;
    if (i < EC) {
        int s = edge_at(ei, i);
        int d = edge_at(ei, EC + i);
        if (d >= 0 && d < NN) {
            int p = atomicAdd(&g_fill[d], 1);
            if (p >= 0 && p < E_MAX) g_col[p] = s;
        }
    }
}

// ------- GEMM1: 256x64 tile, 8x8/thread, FFMA2; alpha epilogue in registers ---
__global__ void __launch_bounds__(256) k_gemm1(
    const float* __restrict__ X, const float* __restrict__ W,
    const float* __restrict__ att_s, const float* __restrict__ att_d) {
    __shared__ __align__(16) float Ast[32 * AST2];  // [kk][row] transposed, 33.0KB
    __shared__ __align__(16) float Bs[32 * 64];     // 8KB
    int tid = threadIdx.x;
    int r0 = blockIdx.x * 256;
    int tx = tid & 7;          // head / col-group: cols tx*8..tx*8+7
    int ty = tid >> 3;         // row-group: rows ty*8..ty*8+7

    unsigned long long acc2[4][8];    // [row-pair p][col c]
    unsigned long long z = pack2(0.f, 0.f);
    #pragma unroll
    for (int p = 0; p < 4; p++)
        #pragma unroll
        for (int c = 0; c < 8; c++) acc2[p][c] = z;

    for (int k0 = 0; k0 < F_IN; k0 += 32) {
        // A: 256 rows x 8 float4 = 2048 slots, 8 per thread
        #pragma unroll
        for (int l = 0; l < 8; l++) {
            int slot = tid + l * 256;
            int row = slot >> 3;             // 0..255
            int f4 = slot & 7;               // 0..7
            int gr = r0 + row;
            float4 v = make_float4(0.f, 0.f, 0.f, 0.f);
            if (gr < NN) v = *(const float4*)(X + (long)gr * F_IN + k0 + f4 * 4);
            Ast[(f4 * 4 + 0) * AST2 + row] = v.x;
            Ast[(f4 * 4 + 1) * AST2 + row] = v.y;
            Ast[(f4 * 4 + 2) * AST2 + row] = v.z;
            Ast[(f4 * 4 + 3) * AST2 + row] = v.w;
        }
        // B: 32 k x 16 float4 = 512 slots, 2 per thread
        #pragma unroll
        for (int l = 0; l < 2; l++) {
            int slot = tid + l * 256;
            int kk = slot >> 4;
            int cv = slot & 15;
            *(float4*)&Bs[kk * 64 + cv * 4] = *(const float4*)(W + (k0 + kk) * HID + cv * 4);
        }
        __syncthreads();
        #pragma unroll
        for (int kk = 0; kk < 32; kk++) {
            float4 b0 = *(const float4*)&Bs[kk * 64 + tx * 8];
            float4 b1 = *(const float4*)&Bs[kk * 64 + tx * 8 + 4];
            unsigned long long br[8];
            br[0] = pack2(b0.x, b0.x); br[1] = pack2(b0.y, b0.y);
            br[2] = pack2(b0.z, b0.z); br[3] = pack2(b0.w, b0.w);
            br[4] = pack2(b1.x, b1.x); br[5] = pack2(b1.y, b1.y);
            br[6] = pack2(b1.z, b1.z); br[7] = pack2(b1.w, b1.w);
            const float* ab = Ast + kk * AST2 + ty * 8;
            #pragma unroll
            for (int p = 0; p < 4; p++) {
                unsigned long long ap = *(const unsigned long long*)(ab + 2 * p);
                #pragma unroll
                for (int c = 0; c < 8; c++)
                    acc2[p][c] = ffma2(ap, br[c], acc2[p][c]);
            }
        }
        __syncthreads();
    }

    // epilogue: thread (ty,tx) owns all 8 channels of head tx for its 8 rows ->
    // h1 store + alpha dots entirely in registers, no smem staging.
    float sA[8], dA[8];
    #pragma unroll
    for (int c = 0; c < 8; c++) {
        sA[c] = __ldg(att_s + tx * C1 + c);
        dA[c] = __ldg(att_d + tx * C1 + c);
    }
    #pragma unroll
    for (int p = 0; p < 4; p++) {
        float lo[8], hi[8];
        #pragma unroll
        for (int c = 0; c < 8; c++) unpack2(acc2[p][c], lo[c], hi[c]);
        int rA = r0 + ty * 8 + 2 * p;
        if (rA < NN) {
            *(float4*)(g_h1 + (long)rA * HID + tx * 8)     = make_float4(lo[0], lo[1], lo[2], lo[3]);
            *(float4*)(g_h1 + (long)rA * HID + tx * 8 + 4) = make_float4(lo[4], lo[5], lo[6], lo[7]);
            float as = 0.f, ad = 0.f;
            #pragma unroll
            for (int c = 0; c < 8; c++) { as += lo[c] * sA[c]; ad += lo[c] * dA[c]; }
            g_as1[rA * H1 + tx] = as;
            g_ad1[rA * H1 + tx] = ad;
        }
        int rB = rA + 1;
        if (rB < NN) {
            *(float4*)(g_h1 + (long)rB * HID + tx * 8)     = make_float4(hi[0], hi[1], hi[2], hi[3]);
            *(float4*)(g_h1 + (long)rB * HID + tx * 8 + 4) = make_float4(hi[4], hi[5], hi[6], hi[7]);
            float as = 0.f, ad = 0.f;
            #pragma unroll
            for (int c = 0; c < 8; c++) { as += hi[c] * sA[c]; ad += hi[c] * dA[c]; }
            g_as1[rB * H1 + tx] = as;
            g_ad1[rB * H1 + tx] = ad;
        }
    }
}

// -------- layer 1 aggregation: shfl-free, 2-edge ILP, single pass + elu -------
// (round-7 form: MLP=2 measured best; 4-wide regressed)
__global__ void k_agg1(const float* __restrict__ b1) {
    int warp = (blockIdx.x * blockDim.x + threadIdx.x) >> 5;
    int lane = threadIdx.x & 31;
    if (warp >= NN) return;
    int d = warp;
    int start = g_rowptr[d], end = g_rowptr[d + 1];
    int h = lane >> 2;                    // head for this lane's channel pair
    float ad = __ldg(g_ad1 + d * H1 + h);

    unsigned long long acc = pack2(0.f, 0.f);
    float den = 0.f;
    int n = end - start;
    int n2 = n & ~1;
    const int* cp = g_col + start;

    #pragma unroll 2
    for (int i = 0; i < n2; i += 2) {
        int s0 = __ldg(cp + i);
        int s1 = __ldg(cp + i + 1);
        float e0 = __ldg(g_as1 + s0 * H1 + h) + ad;
        float e1 = __ldg(g_as1 + s1 * H1 + h) + ad;
        e0 = (e0 > 0.f) ? e0 : NEG_SLOPE * e0;
        e1 = (e1 > 0.f) ? e1 : NEG_SLOPE * e1;
        float w0 = __expf(e0);
        float w1 = __expf(e1);
        unsigned long long hv0 = *(const unsigned long long*)(g_h1 + (long)s0 * HID + 2 * lane);
        unsigned long long hv1 = *(const unsigned long long*)(g_h1 + (long)s1 * HID + 2 * lane);
        den += w0 + w1;
        acc = ffma2(hv0, pack2(w0, w0), acc);
        acc = ffma2(hv1, pack2(w1, w1), acc);
    }
    if (n2 < n) {
        int s0 = __ldg(cp + n2);
        float e0 = __ldg(g_as1 + s0 * H1 + h) + ad;
        e0 = (e0 > 0.f) ? e0 : NEG_SLOPE * e0;
        float w0 = __expf(e0);
        unsigned long long hv0 = *(const unsigned long long*)(g_h1 + (long)s0 * HID + 2 * lane);
        den += w0;
        acc = ffma2(hv0, pack2(w0, w0), acc);
    }
    float inv = 1.0f / den;
    float lo, hi;
    unpack2(acc, lo, hi);
    float v0 = lo * inv + __ldg(b1 + 2 * lane);
    float v1 = hi * inv + __ldg(b1 + 2 * lane + 1);
    v0 = (v0 > 0.f) ? v0 : expm1f(v0);
    v1 = (v1 > 0.f) ? v1 : expm1f(v1);
    *(float2*)(g_h1o + (long)d * HID + 2 * lane) = make_float2(v0, v1);
}

// ---------------- GEMM2 (FFMA2 inner) + alpha2 --------------------------------
__global__ void __launch_bounds__(128) k_gemm2(
    const float* __restrict__ W2,
    const float* __restrict__ att_s2, const float* __restrict__ att_d2) {
    __shared__ __align__(16) float Xs[128][65];
    __shared__ __align__(16) float Ws[HID][NC];
    __shared__ float Sa[NC], Sd[NC];
    int tid = threadIdx.x;
    int r0 = blockIdx.x * 128;
    for (int f = tid; f < HID * NC; f += 128) Ws[f / NC][f % NC] = W2[f];
    if (tid < NC) { Sa[tid] = att_s2[tid]; Sd[tid] = att_d2[tid]; }
    for (int f = tid; f < 128 * HID; f += 128) {
        int rr = f >> 6, cc = f & 63;
        int gr = r0 + rr;
        Xs[rr][cc] = (gr < NN) ? g_h1o[(long)gr * HID + cc] : 0.f;
    }
    __syncthreads();
    int r = r0 + tid;
    unsigned long long acc2[NC / 2];
    unsigned long long z = pack2(0.f, 0.f);
    #pragma unroll
    for (int c = 0; c < NC / 2; c++) acc2[c] = z;
    #pragma unroll 4
    for (int k = 0; k < HID; k++) {
        float xv = Xs[tid][k];
        unsigned long long xp = pack2(xv, xv);
        const unsigned long long* wp = (const unsigned long long*)&Ws[k][0];
        #pragma unroll
        for (int c = 0; c < NC / 2; c++) acc2[c] = ffma2(xp, wp[c], acc2[c]);
    }
    if (r < NN) {
        float a = 0.f, dd = 0.f;
        #pragma unroll
        for (int c = 0; c < NC / 2; c++) {
            float lo, hi;
            unpack2(acc2[c], lo, hi);
            g_h2[(long)r * NC + 2 * c]     = lo;
            g_h2[(long)r * NC + 2 * c + 1] = hi;
            a  += lo * Sa[2 * c] + hi * Sa[2 * c + 1];
            dd += lo * Sd[2 * c] + hi * Sd[2 * c + 1];
        }
        g_as2[r] = a;
        g_ad2[r] = dd;
    }
}

// --------- layer 2 aggregation: 2-edge ILP, single pass + log_softmax ---------
__global__ void k_agg2(const float* __restrict__ b2, float* __restrict__ out) {
    int warp = (blockIdx.x * blockDim.x + threadIdx.x) >> 5;
    int lane = threadIdx.x & 31;
    if (warp >= NN) return;
    int d = warp;
    int start = g_rowptr[d], end = g_rowptr[d + 1];
    float ad = __ldg(g_ad2 + d);
    bool act = lane < 20;

    unsigned long long acc = pack2(0.f, 0.f);
    float den = 0.f;
    int n = end - start;
    int n2 = n & ~1;
    const int* cp = g_col + start;

    #pragma unroll 2
    for (int i = 0; i < n2; i += 2) {
        int s0 = __ldg(cp + i);
        int s1 = __ldg(cp + i + 1);
        float e0 = __ldg(g_as2 + s0) + ad;
        float e1 = __ldg(g_as2 + s1) + ad;
        e0 = (e0 > 0.f) ? e0 : NEG_SLOPE * e0;
        e1 = (e1 > 0.f) ? e1 : NEG_SLOPE * e1;
        float w0 = __expf(e0);
        float w1 = __expf(e1);
        den += w0 + w1;
        if (act) {
            unsigned long long hv0 = *(const unsigned long long*)(g_h2 + (long)s0 * NC + 2 * lane);
            unsigned long long hv1 = *(const unsigned long long*)(g_h2 + (long)s1 * NC + 2 * lane);
            acc = ffma2(hv0, pack2(w0, w0), acc);
            acc = ffma2(hv1, pack2(w1, w1), acc);
        }
    }
    if (n2 < n) {
        int s0 = __ldg(cp + n2);
        float e0 = __ldg(g_as2 + s0) + ad;
        e0 = (e0 > 0.f) ? e0 : NEG_SLOPE * e0;
        float w0 = __expf(e0);
        den += w0;
        if (act) {
            unsigned long long hv0 = *(const unsigned long long*)(g_h2 + (long)s0 * NC + 2 * lane);
            acc = ffma2(hv0, pack2(w0, w0), acc);
        }
    }
    float inv = 1.0f / den;
    float lo, hi;
    unpack2(acc, lo, hi);
    float v0 = act ? (lo * inv + __ldg(b2 + 2 * lane))     : -3.0e38f;
    float v1 = act ? (hi * inv + __ldg(b2 + 2 * lane + 1)) : -3.0e38f;

    float m = fmaxf(v0, v1);
    #pragma unroll
    for (int o = 16; o >= 1; o >>= 1) m = fmaxf(m, __shfl_xor_sync(0xffffffffu, m, o));
    float se = act ? (__expf(v0 - m) + __expf(v1 - m)) : 0.f;
    #pragma unroll
    for (int o = 16; o >= 1; o >>= 1) se += __shfl_xor_sync(0xffffffffu, se, o);
    float lse = m + logf(se);

    if (act)
        *(float2*)(out + (long)d * NC + 2 * lane) = make_float2(v0 - lse, v1 - lse);
}

// -----------------------------------------------------------------------------
extern "C" void kernel_launch(void* const* d_in, const int* in_sizes, int n_in,
                              void* d_out, int out_size) {
    const float* x        = (const float*)d_in[0];
    const float* W1       = (const float*)d_in[1];
    const float* att_src1 = (const float*)d_in[2];
    const float* att_dst1 = (const float*)d_in[3];
    const float* b1       = (const float*)d_in[4];
    const float* W2       = (const float*)d_in[5];
    const float* att_src2 = (const float*)d_in[6];
    const float* att_dst2 = (const float*)d_in[7];
    const float* b2       = (const float*)d_in[8];
    const void*  ei       = d_in[9];
    float* out = (float*)d_out;

    int EC = in_sizes[9] / 2;
    if (EC > E_MAX) EC = E_MAX;
    int nblocks = (NN + 1023) / 1024;

    cudaStream_t side;
    cudaStreamCreateWithFlags(&side, cudaStreamNonBlocking);
    cudaEvent_t evFork, evJoin;
    cudaEventCreateWithFlags(&evFork, cudaEventDisableTiming);
    cudaEventCreateWithFlags(&evJoin, cudaEventDisableTiming);

    cudaEventRecord(evFork, 0);
    cudaStreamWaitEvent(side, evFork, 0);
    k_gemm1<<<(NN + 255) / 256, 256, 0, side>>>(x, W1, att_src1, att_dst1);
    cudaEventRecord(evJoin, side);

    k_init<<<(NN + 255) / 256, 256>>>(ei, EC);
    k_hist<<<(EC + 255) / 256, 256>>>(ei, EC);
    k_scan_block<<<nblocks, 1024>>>();
    k_scan_tops<<<1, 32>>>(nblocks);
    k_scan_fix<<<nblocks, 1024>>>(EC);
    k_scatter<<<(EC + 255) / 256, 256>>>(ei, EC);

    cudaStreamWaitEvent(0, evJoin, 0);
    k_agg1<<<(NN * 32 + 255) / 256, 256>>>(b1);
    k_gemm2<<<(NN + 127) / 128, 128>>>(W2, att_src2, att_dst2);
    k_agg2<<<(NN * 32 + 255) / 256, 256>>>(b2, out);
}

// round 10
// speedup vs baseline: 1.0234x; 1.0234x over previous
#include <cuda_runtime.h>
#include <cuda_bf16.h>
#include <math.h>

#define NN      100000
#define F_IN    256
#define HID     64
#define H1      8
#define C1      8
#define NC      40
#define E_MAX   1700000
#define NEG_SLOPE 0.2f
#define AST     132

// ---------------- packed f32x2 helpers ----------------------------------------
__device__ __forceinline__ unsigned long long ffma2(
    unsigned long long a, unsigned long long b, unsigned long long c) {
    unsigned long long d;
    asm("fma.rn.f32x2 %0, %1, %2, %3;" : "=l"(d) : "l"(a), "l"(b), "l"(c));
    return d;
}
__device__ __forceinline__ unsigned long long pack2(float lo, float hi) {
    unsigned long long d;
    asm("mov.b64 %0, {%1, %2};" : "=l"(d) : "f"(lo), "f"(hi));
    return d;
}
__device__ __forceinline__ void unpack2(unsigned long long v, float& lo, float& hi) {
    asm("mov.b64 {%0, %1}, %2;" : "=f"(lo), "=f"(hi) : "l"(v));
}

// ---------------- scratch -----------------------------------------------------
__device__ int   g_is64;
__device__ int   g_deg[NN];
__device__ int   g_rowptr[NN + 1];
__device__ int   g_fill[NN];
__device__ int   g_col[E_MAX];
__device__ int   g_bsum[256];
__device__ float g_h1[(long)NN * HID];
__device__ float g_as1[NN * H1];
__device__ float g_ad1[NN * H1];
__device__ float g_h2[(long)NN * NC];
__device__ float g_as2[NN];
__device__ float g_ad2[NN];

// -------- init: zero degrees + edge dtype detection (block 0) -----------------
__global__ void k_init(const void* ei, int EC) {
    int i = blockIdx.x * blockDim.x + threadIdx.x;
    if (i < NN) g_deg[i] = 0;
    if (blockIdx.x == 0) {
        __shared__ int bad;
        if (threadIdx.x == 0) bad = 0;
        __syncthreads();
        const long long* p = (const long long*)ei;
        int n = EC < 256 ? EC : 256;
        if ((int)threadIdx.x < n) {
            long long v = p[threadIdx.x];
            if (v < 0 || v >= NN) atomicExch(&bad, 1);
        }
        __syncthreads();
        if (threadIdx.x == 0) g_is64 = bad ? 0 : 1;
    }
}

__device__ __forceinline__ int edge_at(const void* ei, int idx) {
    return g_is64 ? (int)((const long long*)ei)[idx] : ((const int*)ei)[idx];
}

// ---------------- CSR build ---------------------------------------------------
__global__ void k_hist(const void* ei, int EC) {
    int i = blockIdx.x * blockDim.x + threadIdx.x;
    if (i < EC) {
        int d = edge_at(ei, EC + i);
        if (d >= 0 && d < NN) atomicAdd(&g_deg[d], 1);
    }
}

__global__ void k_scan_block() {
    __shared__ int ws[32];
    int tid = threadIdx.x;
    int gid = blockIdx.x * 1024 + tid;
    int v = (gid < NN) ? g_deg[gid] : 0;
    int x = v;
    #pragma unroll
    for (int o = 1; o < 32; o <<= 1) {
        int t = __shfl_up_sync(0xffffffffu, x, o);
        if ((tid & 31) >= o) x += t;
    }
    if ((tid & 31) == 31) ws[tid >> 5] = x;
    __syncthreads();
    if (tid < 32) {
        int w = ws[tid];
        int y = w;
        #pragma unroll
        for (int o = 1; o < 32; o <<= 1) {
            int t = __shfl_up_sync(0xffffffffu, y, o);
            if (tid >= o) y += t;
        }
        ws[tid] = y - w;
    }
    __syncthreads();
    int incl = x + ws[tid >> 5];
    if (gid < NN) g_rowptr[gid] = incl - v;
    if (tid == 1023) g_bsum[blockIdx.x] = incl;
}

__global__ void k_scan_tops(int nblocks) {
    int lane = threadIdx.x;
    int run = 0;
    for (int base = 0; base < nblocks; base += 32) {
        int idx = base + lane;
        int v = (idx < nblocks) ? g_bsum[idx] : 0;
        int x = v;
        #pragma unroll
        for (int o = 1; o < 32; o <<= 1) {
            int t = __shfl_up_sync(0xffffffffu, x, o);
            if (lane >= o) x += t;
        }
        if (idx < nblocks) g_bsum[idx] = run + x - v;
        run += __shfl_sync(0xffffffffu, x, 31);
    }
}

__global__ void k_scan_fix(int EC) {
    int gid = blockIdx.x * 1024 + threadIdx.x;
    if (gid < NN) {
        int v = g_rowptr[gid] + g_bsum[gid >> 10];
        g_rowptr[gid] = v;
        g_fill[gid] = v;
    }
    if (gid == 0) g_rowptr[NN] = EC;
}

__global__ void k_scatter(const void* ei, int EC) {
    int i = blockIdx.x * blockDim.x + threadIdx.x;
    if (i < EC) {
        int s = edge_at(ei, i);
        int d = edge_at(ei, EC + i);
        if (d >= 0 && d < NN) {
            int p = atomicAdd(&g_fill[d], 1);
            if (p >= 0 && p < E_MAX) g_col[p] = s;
        }
    }
}

// ------- GEMM1 (R7 form: 128x64 tile, FFMA2 inner) + fused alpha epilogue -----
__global__ void __launch_bounds__(256) k_gemm1(
    const float* __restrict__ X, const float* __restrict__ W,
    const float* __restrict__ att_s, const float* __restrict__ att_d) {
    __shared__ __align__(16) float sm[128 * 65];
    float* Ast = sm;                  // transposed: [kk][row], stride AST=132
    float* Bs  = sm + 32 * AST;
    int tid = threadIdx.x;
    int r0 = blockIdx.x * 128;
    int tx = tid & 15, ty = tid >> 4;

    unsigned long long acc2[4][4];
    unsigned long long z = pack2(0.f, 0.f);
    #pragma unroll
    for (int p = 0; p < 4; p++)
        #pragma unroll
        for (int c = 0; c < 4; c++) acc2[p][c] = z;

    for (int k0 = 0; k0 < F_IN; k0 += 32) {
        #pragma unroll
        for (int l = 0; l < 4; l++) {
            int slot = tid + l * 256;
            int row = slot >> 3;
            int f4 = slot & 7;
            int gr = r0 + row;
            float4 v = make_float4(0.f, 0.f, 0.f, 0.f);
            if (gr < NN) v = *(const float4*)(X + (long)gr * F_IN + k0 + f4 * 4);
            Ast[(f4 * 4 + 0) * AST + row] = v.x;
            Ast[(f4 * 4 + 1) * AST + row] = v.y;
            Ast[(f4 * 4 + 2) * AST + row] = v.z;
            Ast[(f4 * 4 + 3) * AST + row] = v.w;
        }
        #pragma unroll
        for (int l = 0; l < 2; l++) {
            int slot = tid + l * 256;
            int kk = slot >> 4;
            int cv = slot & 15;
            *(float4*)&Bs[kk * 64 + cv * 4] = *(const float4*)(W + (k0 + kk) * HID + cv * 4);
        }
        __syncthreads();
        #pragma unroll
        for (int kk = 0; kk < 32; kk++) {
            float4 bv = *(const float4*)&Bs[kk * 64 + tx * 4];
            unsigned long long br[4];
            br[0] = pack2(bv.x, bv.x);
            br[1] = pack2(bv.y, bv.y);
            br[2] = pack2(bv.z, bv.z);
            br[3] = pack2(bv.w, bv.w);
            const float* ab = Ast + kk * AST + ty * 8;
            #pragma unroll
            for (int p = 0; p < 4; p++) {
                unsigned long long ap = *(const unsigned long long*)(ab + 2 * p);
                acc2[p][0] = ffma2(ap, br[0], acc2[p][0]);
                acc2[p][1] = ffma2(ap, br[1], acc2[p][1]);
                acc2[p][2] = ffma2(ap, br[2], acc2[p][2]);
                acc2[p][3] = ffma2(ap, br[3], acc2[p][3]);
            }
        }
        __syncthreads();
    }

    float* hbuf = sm;                 // [128][65]
    #pragma unroll
    for (int p = 0; p < 4; p++) {
        float lo[4], hi[4];
        #pragma unroll
        for (int c = 0; c < 4; c++) unpack2(acc2[p][c], lo[c], hi[c]);
        int lr = ty * 8 + 2 * p;
        int gr = r0 + lr;
        #pragma unroll
        for (int c = 0; c < 4; c++) {
            hbuf[lr * 65 + tx * 4 + c] = lo[c];
            hbuf[(lr + 1) * 65 + tx * 4 + c] = hi[c];
        }
        if (gr < NN) {
            #pragma unroll
            for (int c = 0; c < 4; c++)
                g_h1[(long)gr * HID + tx * 4 + c] = lo[c];
        }
        if (gr + 1 < NN) {
            #pragma unroll
            for (int c = 0; c < 4; c++)
                g_h1[(long)(gr + 1) * HID + tx * 4 + c] = hi[c];
        }
    }
    __syncthreads();

    #pragma unroll
    for (int t = 0; t < 4; t++) {
        int item = tid + t * 256;
        int lr = item >> 3, h = item & 7;
        int gr = r0 + lr;
        if (gr < NN) {
            const float* hp = hbuf + lr * 65 + h * C1;
            float as = 0.f, ad = 0.f;
            #pragma unroll
            for (int c = 0; c < C1; c++) {
                float hv = hp[c];
                as += hv * __ldg(att_s + h * C1 + c);
                ad += hv * __ldg(att_d + h * C1 + c);
            }
            g_as1[gr * H1 + h] = as;
            g_ad1[gr * H1 + h] = ad;
        }
    }
}

// ---- fused: layer-1 aggregation (R7 loop) + elu + GEMM2 + alpha2, per warp ----
// Phase A: warp-per-dst softmax-weighted gather (identical to R7 k_agg1).
// Phase B: h1o row staged in per-warp SMEM; lanes 0..19 each compute a channel
//          pair of h2 = h1o @ W2 (W2 staged block-wide as u64 pairs), then
//          as2/ad2 by butterfly reduction. Same k-order/pairing as old k_gemm2.
__global__ void __launch_bounds__(256) k_agg1g2(
    const float* __restrict__ b1, const float* __restrict__ W2,
    const float* __restrict__ att_s2, const float* __restrict__ att_d2) {
    __shared__ __align__(16) unsigned long long Wp[HID][NC / 2];  // 10.24KB
    __shared__ float Sa[NC], Sd[NC];
    __shared__ __align__(16) float hb[8][HID];                    // per-warp h1o row

    int tid = threadIdx.x;
    // stage W2 as pairs + att vectors (once per block)
    for (int i = tid; i < HID * (NC / 2); i += 256) {
        int k = i / (NC / 2), j = i % (NC / 2);
        float2 w = *(const float2*)(W2 + k * NC + 2 * j);
        Wp[k][j] = pack2(w.x, w.y);
    }
    if (tid < NC) { Sa[tid] = __ldg(att_s2 + tid); Sd[tid] = __ldg(att_d2 + tid); }
    __syncthreads();

    int warp = (blockIdx.x * blockDim.x + tid) >> 5;
    int wslot = (tid >> 5) & 7;
    int lane = tid & 31;
    if (warp >= NN) return;
    int d = warp;
    int start = g_rowptr[d], end = g_rowptr[d + 1];
    int h = lane >> 2;
    float ad = __ldg(g_ad1 + d * H1 + h);

    unsigned long long acc = pack2(0.f, 0.f);
    float den = 0.f;
    int n = end - start;
    int n2 = n & ~1;
    const int* cp = g_col + start;

    #pragma unroll 2
    for (int i = 0; i < n2; i += 2) {
        int s0 = __ldg(cp + i);
        int s1 = __ldg(cp + i + 1);
        float e0 = __ldg(g_as1 + s0 * H1 + h) + ad;
        float e1 = __ldg(g_as1 + s1 * H1 + h) + ad;
        e0 = (e0 > 0.f) ? e0 : NEG_SLOPE * e0;
        e1 = (e1 > 0.f) ? e1 : NEG_SLOPE * e1;
        float w0 = __expf(e0);
        float w1 = __expf(e1);
        unsigned long long hv0 = *(const unsigned long long*)(g_h1 + (long)s0 * HID + 2 * lane);
        unsigned long long hv1 = *(const unsigned long long*)(g_h1 + (long)s1 * HID + 2 * lane);
        den += w0 + w1;
        acc = ffma2(hv0, pack2(w0, w0), acc);
        acc = ffma2(hv1, pack2(w1, w1), acc);
    }
    if (n2 < n) {
        int s0 = __ldg(cp + n2);
        float e0 = __ldg(g_as1 + s0 * H1 + h) + ad;
        e0 = (e0 > 0.f) ? e0 : NEG_SLOPE * e0;
        float w0 = __expf(e0);
        unsigned long long hv0 = *(const unsigned long long*)(g_h1 + (long)s0 * HID + 2 * lane);
        den += w0;
        acc = ffma2(hv0, pack2(w0, w0), acc);
    }
    float inv = 1.0f / den;
    float lo, hi;
    unpack2(acc, lo, hi);
    float v0 = lo * inv + __ldg(b1 + 2 * lane);
    float v1 = hi * inv + __ldg(b1 + 2 * lane + 1);
    v0 = (v0 > 0.f) ? v0 : expm1f(v0);
    v1 = (v1 > 0.f) ? v1 : expm1f(v1);

    // phase B: stage h1o row, compute h2 row + as2/ad2 in-warp
    *(float2*)&hb[wslot][2 * lane] = make_float2(v0, v1);
    __syncwarp();

    float pa = 0.f, pd = 0.f;
    if (lane < NC / 2) {
        unsigned long long a2 = pack2(0.f, 0.f);
        const float* hr = hb[wslot];
        #pragma unroll 4
        for (int k = 0; k < HID; k++) {
            float xv = hr[k];                       // warp-broadcast LDS
            a2 = ffma2(pack2(xv, xv), Wp[k][lane], a2);
        }
        float c0, c1;
        unpack2(a2, c0, c1);
        *(float2*)(g_h2 + (long)d * NC + 2 * lane) = make_float2(c0, c1);
        pa = c0 * Sa[2 * lane] + c1 * Sa[2 * lane + 1];
        pd = c0 * Sd[2 * lane] + c1 * Sd[2 * lane + 1];
    }
    #pragma unroll
    for (int o = 16; o >= 1; o >>= 1) {
        pa += __shfl_xor_sync(0xffffffffu, pa, o);
        pd += __shfl_xor_sync(0xffffffffu, pd, o);
    }
    if (lane == 0) {
        g_as2[d] = pa;
        g_ad2[d] = pd;
    }
}

// --------- layer 2 aggregation: 2-edge ILP, single pass + log_softmax ---------
__global__ void k_agg2(const float* __restrict__ b2, float* __restrict__ out) {
    int warp = (blockIdx.x * blockDim.x + threadIdx.x) >> 5;
    int lane = threadIdx.x & 31;
    if (warp >= NN) return;
    int d = warp;
    int start = g_rowptr[d], end = g_rowptr[d + 1];
    float ad = __ldg(g_ad2 + d);
    bool act = lane < 20;

    unsigned long long acc = pack2(0.f, 0.f);
    float den = 0.f;
    int n = end - start;
    int n2 = n & ~1;
    const int* cp = g_col + start;

    #pragma unroll 2
    for (int i = 0; i < n2; i += 2) {
        int s0 = __ldg(cp + i);
        int s1 = __ldg(cp + i + 1);
        float e0 = __ldg(g_as2 + s0) + ad;
        float e1 = __ldg(g_as2 + s1) + ad;
        e0 = (e0 > 0.f) ? e0 : NEG_SLOPE * e0;
        e1 = (e1 > 0.f) ? e1 : NEG_SLOPE * e1;
        float w0 = __expf(e0);
        float w1 = __expf(e1);
        den += w0 + w1;
        if (act) {
            unsigned long long hv0 = *(const unsigned long long*)(g_h2 + (long)s0 * NC + 2 * lane);
            unsigned long long hv1 = *(const unsigned long long*)(g_h2 + (long)s1 * NC + 2 * lane);
            acc = ffma2(hv0, pack2(w0, w0), acc);
            acc = ffma2(hv1, pack2(w1, w1), acc);
        }
    }
    if (n2 < n) {
        int s0 = __ldg(cp + n2);
        float e0 = __ldg(g_as2 + s0) + ad;
        e0 = (e0 > 0.f) ? e0 : NEG_SLOPE * e0;
        float w0 = __expf(e0);
        den += w0;
        if (act) {
            unsigned long long hv0 = *(const unsigned long long*)(g_h2 + (long)s0 * NC + 2 * lane);
            acc = ffma2(hv0, pack2(w0, w0), acc);
        }
    }
    float inv = 1.0f / den;
    float lo, hi;
    unpack2(acc, lo, hi);
    float v0 = act ? (lo * inv + __ldg(b2 + 2 * lane))     : -3.0e38f;
    float v1 = act ? (hi * inv + __ldg(b2 + 2 * lane + 1)) : -3.0e38f;

    float m = fmaxf(v0, v1);
    #pragma unroll
    for (int o = 16; o >= 1; o >>= 1) m = fmaxf(m, __shfl_xor_sync(0xffffffffu, m, o));
    float se = act ? (__expf(v0 - m) + __expf(v1 - m)) : 0.f;
    #pragma unroll
    for (int o = 16; o >= 1; o >>= 1) se += __shfl_xor_sync(0xffffffffu, se, o);
    float lse = m + logf(se);

    if (act)
        *(float2*)(out + (long)d * NC + 2 * lane) = make_float2(v0 - lse, v1 - lse);
}

// -----------------------------------------------------------------------------
extern "C" void kernel_launch(void* const* d_in, const int* in_sizes, int n_in,
                              void* d_out, int out_size) {
    const float* x        = (const float*)d_in[0];
    const float* W1       = (const float*)d_in[1];
    const float* att_src1 = (const float*)d_in[2];
    const float* att_dst1 = (const float*)d_in[3];
    const float* b1       = (const float*)d_in[4];
    const float* W2       = (const float*)d_in[5];
    const float* att_src2 = (const float*)d_in[6];
    const float* att_dst2 = (const float*)d_in[7];
    const float* b2       = (const float*)d_in[8];
    const void*  ei       = d_in[9];
    float* out = (float*)d_out;

    int EC = in_sizes[9] / 2;
    if (EC > E_MAX) EC = E_MAX;
    int nblocks = (NN + 1023) / 1024;

    cudaStream_t side;
    cudaStreamCreateWithFlags(&side, cudaStreamNonBlocking);
    cudaEvent_t evFork, evJoin;
    cudaEventCreateWithFlags(&evFork, cudaEventDisableTiming);
    cudaEventCreateWithFlags(&evJoin, cudaEventDisableTiming);

    cudaEventRecord(evFork, 0);
    cudaStreamWaitEvent(side, evFork, 0);
    k_gemm1<<<(NN + 127) / 128, 256, 0, side>>>(x, W1, att_src1, att_dst1);
    cudaEventRecord(evJoin, side);

    k_init<<<(NN + 255) / 256, 256>>>(ei, EC);
    k_hist<<<(EC + 255) / 256, 256>>>(ei, EC);
    k_scan_block<<<nblocks, 1024>>>();
    k_scan_tops<<<1, 32>>>(nblocks);
    k_scan_fix<<<nblocks, 1024>>>(EC);
    k_scatter<<<(EC + 255) / 256, 256>>>(ei, EC);

    cudaStreamWaitEvent(0, evJoin, 0);
    k_agg1g2<<<(NN * 32 + 255) / 256, 256>>>(b1, W2, att_src2, att_dst2);
    k_agg2<<<(NN * 32 + 255) / 256, 256>>>(b2, out);
}